// round 6
// baseline (speedup 1.0000x reference)
#include <cuda_runtime.h>
#include <cuda_fp16.h>
#include <math.h>

#define B_    64
#define S_    1024
#define D_    800
#define MS_   16
#define T_    32
#define H_    200
#define NS_   12
#define NSPAN (B_*MS_)        // 1024
#define MROWS (NSPAN*T_)      // 32768
#define KDIM  D_              // 800
#define KP    832             // GEMM K padded
#define KP2   (KP/2)
#define G4H   (4*H_)          // 800
#define NCOLS 1600
#define NCPAD 1664
#define KC    64
#define KC2   (KC/2)
#define PITCH 36              // GEMM smem pitch (u32)

// ---- LSTM tensor-core geometry ----
#define GSP    16             // spans per group
#define RCOLS  832            // 4 gates x 208 padded units
#define RKP    104            // 208 k (padded) / 2 kpairs
#define NCHUNK 13             // 16-k chunks
#define BPITCH_L 12           // B chunk smem pitch (u32): banks ok, 48B align
#define APITCH_L 108          // hA pitch (u32): 108%8==4 -> distinct banks
#define ZPITCH   836          // zbuf pitch (floats): 836%32==4

// -------- scratch (static device arrays; no runtime alloc) ------------------
__device__ float    g_Z[2][(size_t)MROWS * G4H];
__device__ unsigned g_A16[(size_t)MROWS * KP2];          // gathered A fp16 pairs
__device__ unsigned g_B16[(size_t)NCPAD * KP2];          // Wih^T n-major fp16 pairs
__device__ unsigned g_Whh16[2 * NCHUNK * RCOLS * 8];     // chunk-major recurrent fp16
__device__ float    g_biasC[NCPAD];
__device__ float    g_feats[(size_t)NSPAN * 2 * H_];
__device__ int      g_rows[MROWS];
__device__ int      g_order[NSPAN];
__device__ int      g_cnt;

__device__ __forceinline__ unsigned pack_h2(float x0, float x1) {
    __half2 h = __floats2half2_rn(x0, x1);
    return *reinterpret_cast<unsigned*>(&h);
}

__device__ __forceinline__ void cp16(unsigned* smem_ptr, const unsigned* gptr) {
    unsigned saddr = (unsigned)__cvta_generic_to_shared(smem_ptr);
    asm volatile("cp.async.cg.shared.global [%0], [%1], 16;" :: "r"(saddr), "l"(gptr));
}

#define MMA_FP16(d, a, b)                                                       \
    asm volatile("mma.sync.aligned.m16n8k16.row.col.f32.f16.f16.f32 "           \
                 "{%0,%1,%2,%3}, {%4,%5,%6,%7}, {%8,%9}, {%0,%1,%2,%3};"        \
                 : "+f"(d[0]), "+f"(d[1]), "+f"(d[2]), "+f"(d[3])               \
                 : "r"(a[0]), "r"(a[1]), "r"(a[2]), "r"(a[3]),                  \
                   "r"(b[0]), "r"(b[1]));

// ---------------------------------------------------------------------------
// Pack: Wih^T -> n-major fp16 pairs; Whh -> chunk-major fp16; biases.
// ---------------------------------------------------------------------------
__global__ void pack_kernel(const float* __restrict__ Wih_f, const float* __restrict__ Whh_f,
                            const float* __restrict__ bih_f, const float* __restrict__ bhh_f,
                            const float* __restrict__ Wih_b, const float* __restrict__ Whh_b,
                            const float* __restrict__ bih_b, const float* __restrict__ bhh_b) {
    int stride = gridDim.x * blockDim.x;
    int tid0   = blockIdx.x * blockDim.x + threadIdx.x;

    for (int idx = tid0; idx < NCPAD * (KP / 8); idx += stride) {
        int j = idx / (KP / 8), q = idx % (KP / 8);
        int k0 = q * 8;
        float xs[8];
#pragma unroll
        for (int e = 0; e < 8; e++) {
            int k = k0 + e;
            float v = 0.f;
            if (j < NCOLS && k < KDIM)
                v = (j < G4H) ? Wih_f[(size_t)j * D_ + k]
                              : Wih_b[(size_t)(j - G4H) * D_ + k];
            xs[e] = v;
        }
        uint4 h4;
        h4.x = pack_h2(xs[0], xs[1]);
        h4.y = pack_h2(xs[2], xs[3]);
        h4.z = pack_h2(xs[4], xs[5]);
        h4.w = pack_h2(xs[6], xs[7]);
        *reinterpret_cast<uint4*>(&g_B16[(size_t)j * KP2 + q * 4]) = h4;
    }

    // Whh pack: write-coalesced order (off fastest, then col, then chunk, dir)
    for (int idx = tid0; idx < 2 * NCHUNK * RCOLS * 8; idx += stride) {
        int off = idx & 7;
        int col = (idx >> 3) % RCOLS;
        int ck  = (idx >> 3) / RCOLS % NCHUNK;
        int dir = idx / (NCHUNK * RCOLS * 8);
        int kp  = ck * 8 + off;
        int gate = col / 208, u = col % 208;
        int k0 = 2 * kp, k1 = 2 * kp + 1;
        float v0 = 0.f, v1 = 0.f;
        if (u < H_) {
            const float* Whh = dir ? Whh_b : Whh_f;
            size_t rowi = (size_t)(gate * H_ + u) * H_;
            if (k0 < H_) v0 = Whh[rowi + k0];
            if (k1 < H_) v1 = Whh[rowi + k1];
        }
        g_Whh16[idx] = pack_h2(v0, v1);
    }

    for (int idx = tid0; idx < NCPAD; idx += stride) {
        float v = 0.f;
        if (idx < NCOLS) {
            int dir = idx / G4H, jj = idx % G4H;
            v = dir ? (bih_b[jj] + bhh_b[jj]) : (bih_f[jj] + bhh_f[jj]);
        }
        g_biasC[idx] = v;
    }
}

// ---------------------------------------------------------------------------
// Prep: prefix-scan lens -> compacted rows; counting-sort spans by length.
// ---------------------------------------------------------------------------
__global__ void prep_kernel(const int* __restrict__ lens) {
    __shared__ int s[NSPAN];
    __shared__ int ll[NSPAN];
    __shared__ int cnt[T_ + 1];
    __shared__ int st[T_ + 1];
    int tid = threadIdx.x;
    int l = min(max(lens[tid], 0), T_);
    s[tid] = l;
    ll[tid] = l;
    if (tid <= T_) cnt[tid] = 0;
    __syncthreads();
    for (int d = 1; d < NSPAN; d <<= 1) {
        int v = (tid >= d) ? s[tid - d] : 0;
        __syncthreads();
        s[tid] += v;
        __syncthreads();
    }
    int off = s[tid] - l;
    for (int t = 0; t < l; t++) g_rows[off + t] = tid * T_ + t;
    if (tid == NSPAN - 1) g_cnt = s[tid];
    atomicAdd(&cnt[l], 1);
    __syncthreads();
    if (tid == 0) {
        int a = 0;
        for (int q = 0; q <= T_; q++) { st[q] = a; a += cnt[q]; }
    }
    __syncthreads();
    if (tid <= T_) {
        int pos = st[tid];
        for (int i = 0; i < NSPAN; i++)
            if (ll[i] == tid) g_order[pos++] = i;
    }
}

// ---------------------------------------------------------------------------
// Gather A once -> fp16 pairs (compacted rows, K zero-padded).
// ---------------------------------------------------------------------------
__global__ void gather_split(const float* __restrict__ hidden,
                             const int*   __restrict__ starts) {
    int idx = blockIdx.x * blockDim.x + threadIdx.x;
    int total = g_cnt * (KP / 8);
    if (idx >= total) return;
    int m = idx / (KP / 8), q = idx % (KP / 8);
    int k0 = q * 8;
    float xs[8];
    if (k0 < KDIM) {
        int r = g_rows[m];
        int sp = r >> 5, t = r & 31;
        int b = sp >> 4, mm = sp & 15;
        int src = min(max(starts[b * MS_ + mm] + t, 0), S_ - 1);
        const float* base = &hidden[((size_t)b * S_ + src) * D_ + k0];
        float4 v0 = *reinterpret_cast<const float4*>(base);
        float4 v1 = *reinterpret_cast<const float4*>(base + 4);
        xs[0] = v0.x; xs[1] = v0.y; xs[2] = v0.z; xs[3] = v0.w;
        xs[4] = v1.x; xs[5] = v1.y; xs[6] = v1.z; xs[7] = v1.w;
    } else {
#pragma unroll
        for (int e = 0; e < 8; e++) xs[e] = 0.f;
    }
    uint4 h4;
    h4.x = pack_h2(xs[0], xs[1]);
    h4.y = pack_h2(xs[2], xs[3]);
    h4.z = pack_h2(xs[4], xs[5]);
    h4.w = pack_h2(xs[6], xs[7]);
    *reinterpret_cast<uint4*>(&g_A16[(size_t)m * KP2 + q * 4]) = h4;
}

// ---------------------------------------------------------------------------
// fp16 input GEMM (unchanged from round 5).
// ---------------------------------------------------------------------------
#define MAT_TILE (128 * PITCH)
#define STG      (2 * MAT_TILE)

extern __shared__ unsigned smem_u[];

__global__ __launch_bounds__(256, 2) void gemm_tc(void) {
    const int cnt = g_cnt;
    const int m0  = blockIdx.y * 128;
    if (m0 >= cnt) return;
    const int n0  = blockIdx.x * 128;

    __shared__ int rowIdx[128];
    int tid = threadIdx.x;
    if (tid < 128) {
        int m = m0 + tid;
        rowIdx[tid] = (m < cnt) ? g_rows[m] : -1;
    }

    float acc[16][4];
#pragma unroll
    for (int i = 0; i < 16; i++)
#pragma unroll
        for (int q = 0; q < 4; q++) acc[i][q] = 0.f;

    int lane = tid & 31, wid = tid >> 5;
    int wm = wid >> 2, wn = wid & 3;
    int g = lane >> 2, tg = lane & 3;

    auto load_stage = [&](int stage, int k0u) {
        unsigned* As = smem_u + stage * STG;
        unsigned* Bs = As + MAT_TILE;
#pragma unroll
        for (int i = 0; i < 4; i++) {
            int id = tid + i * 256;
            int m = id >> 3, c = id & 7;
            cp16(&As[m * PITCH + c * 4], &g_A16[(size_t)(m0 + m) * KP2 + k0u + c * 4]);
        }
#pragma unroll
        for (int i = 0; i < 4; i++) {
            int id = tid + i * 256;
            int n = id >> 3, c = id & 7;
            cp16(&Bs[n * PITCH + c * 4], &g_B16[(size_t)(n0 + n) * KP2 + k0u + c * 4]);
        }
    };

    const int NITER = KP / KC;
    load_stage(0, 0);
    asm volatile("cp.async.commit_group;");

    for (int it = 0; it < NITER; it++) {
        if (it + 1 < NITER) load_stage((it + 1) & 1, (it + 1) * KC2);
        asm volatile("cp.async.commit_group;");
        asm volatile("cp.async.wait_group 1;");
        __syncthreads();

        const unsigned* As = smem_u + (it & 1) * STG;
        const unsigned* Bs = As + MAT_TILE;

#pragma unroll
        for (int ks = 0; ks < 4; ks++) {
            int kp = ks * 8;
            unsigned af[4][4];
#pragma unroll
            for (int mt = 0; mt < 4; mt++) {
                int r0 = wm * 64 + mt * 16 + g;
                const unsigned* A0 = As + r0 * PITCH + kp + tg;
                af[mt][0] = A0[0];
                af[mt][1] = A0[8 * PITCH];
                af[mt][2] = A0[4];
                af[mt][3] = A0[8 * PITCH + 4];
            }
            unsigned bf[4][2];
#pragma unroll
            for (int nt = 0; nt < 4; nt++) {
                int c = wn * 32 + nt * 8 + g;
                const unsigned* B0 = Bs + c * PITCH + kp + tg;
                bf[nt][0] = B0[0];
                bf[nt][1] = B0[4];
            }
#pragma unroll
            for (int mt = 0; mt < 4; mt++)
#pragma unroll
                for (int nt = 0; nt < 4; nt++)
                    MMA_FP16(acc[mt * 4 + nt], af[mt], bf[nt]);
        }
        __syncthreads();
    }

#pragma unroll
    for (int mt = 0; mt < 4; mt++) {
        int lr0 = wm * 64 + mt * 16 + g;
#pragma unroll
        for (int nt = 0; nt < 4; nt++) {
            int c = n0 + wn * 32 + nt * 8 + tg * 2;
            if (c >= NCOLS) continue;
            float* a = acc[mt * 4 + nt];
            float2 bias = *reinterpret_cast<const float2*>(&g_biasC[c]);
            int dirb = (c >= G4H);
            int cc   = dirb ? (c - G4H) : c;
#pragma unroll
            for (int h = 0; h < 2; h++) {
                int lr = lr0 + h * 8;
                if (m0 + lr < cnt) {
                    float2 v;
                    v.x = a[h * 2 + 0] + bias.x;
                    v.y = a[h * 2 + 1] + bias.y;
                    int rid = rowIdx[lr];
                    *reinterpret_cast<float2*>(&g_Z[dirb][(size_t)rid * G4H + cc]) = v;
                }
            }
        }
    }
}

// ---------------------------------------------------------------------------
// Tensor-core LSTM. 16 sorted spans per CTA, grid (64, 2).
// Per step: z_rec[16,832] = [h_hi;h_lo](fp16) @ Whh16 via m16n8k16, weights
// streamed through a warp-private cp.async triple-buffer (no barriers),
// then gate math with c/feat in registers.
// ---------------------------------------------------------------------------
__device__ __forceinline__ float fast_sig(float x)  { return 1.f / (1.f + __expf(-x)); }
__device__ __forceinline__ float fast_tanh(float x) {
    float t = __expf(-2.f * x);
    return __fdividef(1.f - t, 1.f + t);
}

#define ZBUF_U32   (GSP * ZPITCH)            // 13376 (floats==u32 count)
#define HA_U32     (GSP * APITCH_L)          // 1728
#define BBUF_U32   (RCOLS * BPITCH_L)        // 9984
#define LSTM_SMEM  ((ZBUF_U32 + 2 * HA_U32 + 3 * BBUF_U32) * 4)   // 187136 B

__global__ __launch_bounds__(256, 1) void lstm_tc(const int* __restrict__ span_lens) {
    float*    zbuf = (float*)smem_u;
    unsigned* hAhi = smem_u + ZBUF_U32;
    unsigned* hAlo = hAhi + HA_U32;
    unsigned* Bb   = hAlo + HA_U32;

    __shared__ int sp_sh[GSP], len_sh[GSP], maxL_sh;

    int tid  = threadIdx.x;
    int lane = tid & 31, w = tid >> 5;
    int g = lane >> 2, tg = lane & 3;
    int dir = blockIdx.y;
    int grp = blockIdx.x;

    if (tid < GSP) {
        int sp = g_order[grp * GSP + tid];
        sp_sh[tid]  = sp;
        len_sh[tid] = min(max(span_lens[sp], 0), T_);
    }
    for (int i = tid; i < 2 * HA_U32; i += 256) hAhi[i] = 0;   // zeros hAhi+hAlo
    __syncthreads();
    if (tid == 0) {
        int m = 0;
#pragma unroll
        for (int p = 0; p < GSP; p++) m = max(m, len_sh[p]);
        maxL_sh = m;
    }
    __syncthreads();
    int maxL = maxL_sh;

    const unsigned* Wd = g_Whh16 + (size_t)dir * NCHUNK * RCOLS * 8;
    const float*    Zd = g_Z[dir];

    float c_st[13], feat[13];
#pragma unroll
    for (int i = 0; i < 13; i++) { c_st[i] = 0.f; feat[i] = 0.f; }

    // warp-private B loader: warp w loads its 104 columns of chunk ck into buf
    auto issueB = [&](int ck, int buf) {
        unsigned* dst = Bb + buf * BBUF_U32;
#pragma unroll
        for (int j = 0; j < 7; j++) {
            int idx = lane + 32 * j;
            if (idx < 208) {
                int col  = w * 104 + (idx >> 1);
                int half = idx & 1;
                cp16(&dst[col * BPITCH_L + half * 4],
                     &Wd[((size_t)ck * RCOLS + col) * 8 + half * 4]);
            }
        }
        asm volatile("cp.async.commit_group;");
    };

    issueB(0, 0); issueB(1, 1); issueB(2, 2);
    int absck = 0;

    for (int s = 0; s < maxL; s++) {
        // stage Z_in into zbuf (gate-padded columns)
        for (int i = tid; i < GSP * 800; i += 256) {
            int span = i / 800, j = i - span * 800;
            int L = len_sh[span];
            int t = dir ? (L - 1 - s) : s;
            if (s >= L) t = 0;
            int row = sp_sh[span] * T_ + t;
            float v = Zd[(size_t)row * G4H + j];
            int gate = j / 200, u = j - gate * 200;
            zbuf[span * ZPITCH + gate * 208 + u] = v;
        }

        float acc[13][4];
#pragma unroll
        for (int n = 0; n < 13; n++) {
            acc[n][0] = 0.f; acc[n][1] = 0.f; acc[n][2] = 0.f; acc[n][3] = 0.f;
        }

        for (int ck = 0; ck < NCHUNK; ck++) {
            asm volatile("cp.async.wait_group 2;");
            int buf = absck % 3;
            const unsigned* Bs = Bb + buf * BBUF_U32;

            const unsigned* Ah = hAhi + g * APITCH_L + ck * 8 + tg;
            const unsigned* Al = hAlo + g * APITCH_L + ck * 8 + tg;
            unsigned a_hi[4] = {Ah[0], Ah[8 * APITCH_L], Ah[4], Ah[8 * APITCH_L + 4]};
            unsigned a_lo[4] = {Al[0], Al[8 * APITCH_L], Al[4], Al[8 * APITCH_L + 4]};
#pragma unroll
            for (int nt = 0; nt < 13; nt++) {
                int cidx = w * 104 + nt * 8 + g;
                const unsigned* Bp = Bs + cidx * BPITCH_L + tg;
                unsigned b[2] = {Bp[0], Bp[4]};
                MMA_FP16(acc[nt], a_hi, b);
                MMA_FP16(acc[nt], a_lo, b);
            }
            // refill just-consumed buffer (warp-synchronous: all lanes' reads done)
            issueB((absck + 3) % NCHUNK, buf);
            absck++;
        }
        __syncthreads();   // staging + all warps' mma done

        // epilogue: zbuf += z_rec
#pragma unroll
        for (int nt = 0; nt < 13; nt++) {
            int cidx = w * 104 + nt * 8 + tg * 2;
            float2* z0 = (float2*)&zbuf[g * ZPITCH + cidx];
            float2* z1 = (float2*)&zbuf[(g + 8) * ZPITCH + cidx];
            float2 v0 = *z0; v0.x += acc[nt][0]; v0.y += acc[nt][1]; *z0 = v0;
            float2 v1 = *z1; v1.x += acc[nt][2]; v1.y += acc[nt][3]; *z1 = v1;
        }
        __syncthreads();   // z complete

        // gate phase: pairs p = span*200 + u
#pragma unroll
        for (int i = 0; i < 13; i++) {
            int p = tid + 256 * i;
            if (p < GSP * H_) {
                int span = p / H_, u = p - span * H_;
                if (s < len_sh[span]) {
                    const float* zr = &zbuf[span * ZPITCH];
                    float zi = zr[u];
                    float zf = zr[208 + u];
                    float zg = zr[416 + u];
                    float zo = zr[624 + u];
                    float ig = fast_sig(zi), fg = fast_sig(zf);
                    float gg = fast_tanh(zg), og = fast_sig(zo);
                    float cn = fg * c_st[i] + ig * gg;
                    c_st[i] = cn;
                    float hn = og * fast_tanh(cn);
                    feat[i] += hn;
                    __half hh = __float2half_rn(hn);
                    __half hl = __float2half_rn(hn - __half2float(hh));
                    ((__half*)hAhi)[span * (2 * APITCH_L) + u] = hh;
                    ((__half*)hAlo)[span * (2 * APITCH_L) + u] = hl;
                }
            }
        }
        __syncthreads();   // hA ready for next step
    }

    asm volatile("cp.async.wait_group 0;");

#pragma unroll
    for (int i = 0; i < 13; i++) {
        int p = tid + 256 * i;
        if (p < GSP * H_) {
            int span = p / H_, u = p - span * H_;
            g_feats[(size_t)sp_sh[span] * (2 * H_) + dir * H_ + u] = feat[i];
        }
    }
}

// ---------------------------------------------------------------------------
// logits
// ---------------------------------------------------------------------------
__global__ __launch_bounds__(192) void logits_kernel(const float* __restrict__ slot_embs,
                                                     const float* __restrict__ slot_mask,
                                                     float* __restrict__ out) {
    __shared__ float f_sm[16][2 * H_];
    __shared__ float se_sm[2 * H_ * NS_];

    int tid = threadIdx.x;
    int n0  = blockIdx.x * 16;

    for (int i = tid; i < 2 * H_ * NS_; i += blockDim.x) se_sm[i] = slot_embs[i];
    for (int i = tid; i < 16 * 2 * H_; i += blockDim.x) {
        int sp = i / (2 * H_), h = i % (2 * H_);
        f_sm[sp][h] = g_feats[(size_t)(n0 + sp) * (2 * H_) + h];
    }
    __syncthreads();

    int sp = tid / NS_, ns = tid % NS_;
    float acc = 0.f;
#pragma unroll 8
    for (int h = 0; h < 2 * H_; h++) acc += f_sm[sp][h] * se_sm[h * NS_ + ns];
    out[(n0 + sp) * NS_ + ns] = acc * slot_mask[n0 + sp];
}

// ---------------------------------------------------------------------------
extern "C" void kernel_launch(void* const* d_in, const int* in_sizes, int n_in,
                              void* d_out, int out_size) {
    const float* hidden    = (const float*)d_in[0];
    const float* Wih_f     = (const float*)d_in[1];
    const float* Whh_f     = (const float*)d_in[2];
    const float* bih_f     = (const float*)d_in[3];
    const float* bhh_f     = (const float*)d_in[4];
    const float* Wih_b     = (const float*)d_in[5];
    const float* Whh_b     = (const float*)d_in[6];
    const float* bih_b     = (const float*)d_in[7];
    const float* bhh_b     = (const float*)d_in[8];
    const float* slot_embs = (const float*)d_in[9];
    const int*   starts    = (const int*)d_in[10];
    const int*   lens      = (const int*)d_in[11];
    const float* slot_mask = (const float*)d_in[12];
    float* out = (float*)d_out;

    const int gemm_smem = 2 * STG * (int)sizeof(unsigned);   // 73728 B
    cudaFuncSetAttribute(gemm_tc, cudaFuncAttributeMaxDynamicSharedMemorySize, gemm_smem);
    cudaFuncSetAttribute(lstm_tc, cudaFuncAttributeMaxDynamicSharedMemorySize, LSTM_SMEM);

    pack_kernel<<<1024, 256>>>(Wih_f, Whh_f, bih_f, bhh_f,
                               Wih_b, Whh_b, bih_b, bhh_b);
    prep_kernel<<<1, NSPAN>>>(lens);

    gather_split<<<(MROWS * (KP / 8) + 255) / 256, 256>>>(hidden, starts);

    dim3 ggrid(NCPAD / 128, MROWS / 128);
    gemm_tc<<<ggrid, 256, gemm_smem>>>();

    dim3 lgrid(NSPAN / GSP, 2);   // 64 x 2
    lstm_tc<<<lgrid, 256, LSTM_SMEM>>>(lens);

    logits_kernel<<<NSPAN / 16, 192>>>(slot_embs, slot_mask, out);
}

// round 7
// speedup vs baseline: 1.3100x; 1.3100x over previous
#include <cuda_runtime.h>
#include <cuda_fp16.h>
#include <math.h>

#define B_    64
#define S_    1024
#define D_    800
#define MS_   16
#define T_    32
#define H_    200
#define NS_   12
#define NSPAN (B_*MS_)        // 1024
#define MROWS (NSPAN*T_)      // 32768
#define KDIM  D_              // 800
#define KP    832             // GEMM K padded
#define KP2   (KP/2)
#define G4H   (4*H_)          // 800
#define NCOLS 1600
#define NCPAD 1664
#define PSPAN 8
#define KC    64
#define KC2   (KC/2)
#define PITCH 36              // GEMM smem pitch (u32)
#define HPITCH 10             // lstm h smem pitch (floats): aligned float2, mild conflicts

typedef unsigned long long ull;

// -------- scratch (static device arrays; no runtime alloc) ------------------
__device__ float    g_Z[2][(size_t)MROWS * G4H];
__device__ unsigned g_A16[(size_t)MROWS * KP2];    // gathered A fp16 pairs
__device__ unsigned g_B16[(size_t)NCPAD * KP2];    // Wih^T n-major fp16 pairs
__device__ float4   g_Wp[2][H_ * H_];              // recurrent weights [dir][k*H+u]
__device__ float    g_biasC[NCPAD];
__device__ float    g_feats[(size_t)NSPAN * 2 * H_];
__device__ int      g_rows[MROWS];
__device__ int      g_order[NSPAN];
__device__ int      g_cnt;

__device__ __forceinline__ unsigned pack_h2(float x0, float x1) {
    __half2 h = __floats2half2_rn(x0, x1);
    return *reinterpret_cast<unsigned*>(&h);
}

__device__ __forceinline__ ull pack_f2(float lo, float hi) {
    ull r;
    asm("mov.b64 %0, {%1, %2};" : "=l"(r) : "f"(lo), "f"(hi));
    return r;
}
__device__ __forceinline__ void unpack_f2(ull v, float& lo, float& hi) {
    asm("mov.b64 {%0, %1}, %2;" : "=f"(lo), "=f"(hi) : "l"(v));
}
#define FMA_X2(d, a, b) \
    asm("fma.rn.f32x2 %0, %1, %2, %0;" : "+l"(d) : "l"(a), "l"(b))

// ---------------------------------------------------------------------------
// Pack: Wih^T -> n-major fp16 pairs; gate-pack Whh (float4); biases.
// ---------------------------------------------------------------------------
__global__ void pack_kernel(const float* __restrict__ Wih_f, const float* __restrict__ Whh_f,
                            const float* __restrict__ bih_f, const float* __restrict__ bhh_f,
                            const float* __restrict__ Wih_b, const float* __restrict__ Whh_b,
                            const float* __restrict__ bih_b, const float* __restrict__ bhh_b) {
    int stride = gridDim.x * blockDim.x;
    int tid0   = blockIdx.x * blockDim.x + threadIdx.x;

    for (int idx = tid0; idx < NCPAD * (KP / 8); idx += stride) {
        int j = idx / (KP / 8), q = idx % (KP / 8);
        int k0 = q * 8;
        float xs[8];
#pragma unroll
        for (int e = 0; e < 8; e++) {
            int k = k0 + e;
            float v = 0.f;
            if (j < NCOLS && k < KDIM)
                v = (j < G4H) ? Wih_f[(size_t)j * D_ + k]
                              : Wih_b[(size_t)(j - G4H) * D_ + k];
            xs[e] = v;
        }
        uint4 h4;
        h4.x = pack_h2(xs[0], xs[1]);
        h4.y = pack_h2(xs[2], xs[3]);
        h4.z = pack_h2(xs[4], xs[5]);
        h4.w = pack_h2(xs[6], xs[7]);
        *reinterpret_cast<uint4*>(&g_B16[(size_t)j * KP2 + q * 4]) = h4;
    }
    for (int idx = tid0; idx < 2 * H_ * H_; idx += stride) {
        int dir = idx / (H_ * H_);
        int rem = idx % (H_ * H_);
        int k = rem / H_, u = rem % H_;
        const float* Whh = dir ? Whh_b : Whh_f;
        float4 v;
        v.x = Whh[(size_t)(0 * H_ + u) * H_ + k];
        v.y = Whh[(size_t)(1 * H_ + u) * H_ + k];
        v.z = Whh[(size_t)(2 * H_ + u) * H_ + k];
        v.w = Whh[(size_t)(3 * H_ + u) * H_ + k];
        g_Wp[dir][k * H_ + u] = v;
    }
    for (int idx = tid0; idx < NCPAD; idx += stride) {
        float v = 0.f;
        if (idx < NCOLS) {
            int dir = idx / G4H, jj = idx % G4H;
            v = dir ? (bih_b[jj] + bhh_b[jj]) : (bih_f[jj] + bhh_f[jj]);
        }
        g_biasC[idx] = v;
    }
}

// ---------------------------------------------------------------------------
// Prep: prefix-scan lens -> compacted rows; parallel stable counting sort
// (match_any warp ranking, no serial bucket scans).
// ---------------------------------------------------------------------------
__global__ void prep_kernel(const int* __restrict__ lens) {
    __shared__ int s[NSPAN];
    __shared__ int wcnt[32][T_ + 1];
    __shared__ int st[T_ + 1];
    __shared__ int tot[T_ + 1];
    int tid = threadIdx.x;
    int lane = tid & 31, w = tid >> 5;
    int l = min(max(lens[tid], 0), T_);
    s[tid] = l;
    for (int b = lane; b <= T_; b += 32) wcnt[w][b] = 0;
    __syncthreads();
    for (int d = 1; d < NSPAN; d <<= 1) {
        int v = (tid >= d) ? s[tid - d] : 0;
        __syncthreads();
        s[tid] += v;
        __syncthreads();
    }
    int off = s[tid] - l;
    for (int t = 0; t < l; t++) g_rows[off + t] = tid * T_ + t;
    if (tid == NSPAN - 1) g_cnt = s[tid];

    unsigned mask = __match_any_sync(0xffffffffu, l);
    int rin = __popc(mask & ((1u << lane) - 1u));
    if (rin == 0) wcnt[w][l] = __popc(mask);
    __syncthreads();
    if (tid <= T_) {
        int acc = 0;
        for (int ww = 0; ww < 32; ww++) {
            int c = wcnt[ww][tid];
            wcnt[ww][tid] = acc;
            acc += c;
        }
        tot[tid] = acc;
    }
    __syncthreads();
    if (tid == 0) {
        int a = 0;
        for (int b = 0; b <= T_; b++) { st[b] = a; a += tot[b]; }
    }
    __syncthreads();
    g_order[st[l] + wcnt[w][l] + rin] = tid;
}

// ---------------------------------------------------------------------------
// Gather A once -> fp16 pairs (compacted rows, K zero-padded).
// ---------------------------------------------------------------------------
__global__ void gather_split(const float* __restrict__ hidden,
                             const int*   __restrict__ starts) {
    int idx = blockIdx.x * blockDim.x + threadIdx.x;
    int total = g_cnt * (KP / 8);
    if (idx >= total) return;
    int m = idx / (KP / 8), q = idx % (KP / 8);
    int k0 = q * 8;
    float xs[8];
    if (k0 < KDIM) {
        int r = g_rows[m];
        int sp = r >> 5, t = r & 31;
        int b = sp >> 4, mm = sp & 15;
        int src = min(max(starts[b * MS_ + mm] + t, 0), S_ - 1);
        const float* base = &hidden[((size_t)b * S_ + src) * D_ + k0];
        float4 v0 = *reinterpret_cast<const float4*>(base);
        float4 v1 = *reinterpret_cast<const float4*>(base + 4);
        xs[0] = v0.x; xs[1] = v0.y; xs[2] = v0.z; xs[3] = v0.w;
        xs[4] = v1.x; xs[5] = v1.y; xs[6] = v1.z; xs[7] = v1.w;
    } else {
#pragma unroll
        for (int e = 0; e < 8; e++) xs[e] = 0.f;
    }
    uint4 h4;
    h4.x = pack_h2(xs[0], xs[1]);
    h4.y = pack_h2(xs[2], xs[3]);
    h4.z = pack_h2(xs[4], xs[5]);
    h4.w = pack_h2(xs[6], xs[7]);
    *reinterpret_cast<uint4*>(&g_A16[(size_t)m * KP2 + q * 4]) = h4;
}

// ---------------------------------------------------------------------------
// fp16 input GEMM (unchanged, known-good 162us).
// ---------------------------------------------------------------------------
#define MMA_FP16(d, a, b)                                                       \
    asm volatile("mma.sync.aligned.m16n8k16.row.col.f32.f16.f16.f32 "           \
                 "{%0,%1,%2,%3}, {%4,%5,%6,%7}, {%8,%9}, {%0,%1,%2,%3};"        \
                 : "+f"(d[0]), "+f"(d[1]), "+f"(d[2]), "+f"(d[3])               \
                 : "r"(a[0]), "r"(a[1]), "r"(a[2]), "r"(a[3]),                  \
                   "r"(b[0]), "r"(b[1]));

__device__ __forceinline__ void cp16(unsigned* smem_ptr, const unsigned* gptr) {
    unsigned saddr = (unsigned)__cvta_generic_to_shared(smem_ptr);
    asm volatile("cp.async.cg.shared.global [%0], [%1], 16;" :: "r"(saddr), "l"(gptr));
}

#define MAT_TILE (128 * PITCH)
#define STG      (2 * MAT_TILE)

extern __shared__ unsigned smem_u[];

__global__ __launch_bounds__(256, 2) void gemm_tc(void) {
    const int cnt = g_cnt;
    const int m0  = blockIdx.y * 128;
    if (m0 >= cnt) return;
    const int n0  = blockIdx.x * 128;

    __shared__ int rowIdx[128];
    int tid = threadIdx.x;
    if (tid < 128) {
        int m = m0 + tid;
        rowIdx[tid] = (m < cnt) ? g_rows[m] : -1;
    }

    float acc[16][4];
#pragma unroll
    for (int i = 0; i < 16; i++)
#pragma unroll
        for (int q = 0; q < 4; q++) acc[i][q] = 0.f;

    int lane = tid & 31, wid = tid >> 5;
    int wm = wid >> 2, wn = wid & 3;
    int g = lane >> 2, tg = lane & 3;

    auto load_stage = [&](int stage, int k0u) {
        unsigned* As = smem_u + stage * STG;
        unsigned* Bs = As + MAT_TILE;
#pragma unroll
        for (int i = 0; i < 4; i++) {
            int id = tid + i * 256;
            int m = id >> 3, c = id & 7;
            cp16(&As[m * PITCH + c * 4], &g_A16[(size_t)(m0 + m) * KP2 + k0u + c * 4]);
        }
#pragma unroll
        for (int i = 0; i < 4; i++) {
            int id = tid + i * 256;
            int n = id >> 3, c = id & 7;
            cp16(&Bs[n * PITCH + c * 4], &g_B16[(size_t)(n0 + n) * KP2 + k0u + c * 4]);
        }
    };

    const int NITER = KP / KC;
    load_stage(0, 0);
    asm volatile("cp.async.commit_group;");

    for (int it = 0; it < NITER; it++) {
        if (it + 1 < NITER) load_stage((it + 1) & 1, (it + 1) * KC2);
        asm volatile("cp.async.commit_group;");
        asm volatile("cp.async.wait_group 1;");
        __syncthreads();

        const unsigned* As = smem_u + (it & 1) * STG;
        const unsigned* Bs = As + MAT_TILE;

#pragma unroll
        for (int ks = 0; ks < 4; ks++) {
            int kp = ks * 8;
            unsigned af[4][4];
#pragma unroll
            for (int mt = 0; mt < 4; mt++) {
                int r0 = wm * 64 + mt * 16 + g;
                const unsigned* A0 = As + r0 * PITCH + kp + tg;
                af[mt][0] = A0[0];
                af[mt][1] = A0[8 * PITCH];
                af[mt][2] = A0[4];
                af[mt][3] = A0[8 * PITCH + 4];
            }
            unsigned bf[4][2];
#pragma unroll
            for (int nt = 0; nt < 4; nt++) {
                int c = wn * 32 + nt * 8 + g;
                const unsigned* B0 = Bs + c * PITCH + kp + tg;
                bf[nt][0] = B0[0];
                bf[nt][1] = B0[4];
            }
#pragma unroll
            for (int mt = 0; mt < 4; mt++)
#pragma unroll
                for (int nt = 0; nt < 4; nt++)
                    MMA_FP16(acc[mt * 4 + nt], af[mt], bf[nt]);
        }
        __syncthreads();
    }

#pragma unroll
    for (int mt = 0; mt < 4; mt++) {
        int lr0 = wm * 64 + mt * 16 + g;
#pragma unroll
        for (int nt = 0; nt < 4; nt++) {
            int c = n0 + wn * 32 + nt * 8 + tg * 2;
            if (c >= NCOLS) continue;
            float* a = acc[mt * 4 + nt];
            float2 bias = *reinterpret_cast<const float2*>(&g_biasC[c]);
            int dirb = (c >= G4H);
            int cc   = dirb ? (c - G4H) : c;
#pragma unroll
            for (int h = 0; h < 2; h++) {
                int lr = lr0 + h * 8;
                if (m0 + lr < cnt) {
                    float2 v;
                    v.x = a[h * 2 + 0] + bias.x;
                    v.y = a[h * 2 + 1] + bias.y;
                    int rid = rowIdx[lr];
                    *reinterpret_cast<float2*>(&g_Z[dirb][(size_t)rid * G4H + cc]) = v;
                }
            }
        }
    }
}

// ---------------------------------------------------------------------------
// SIMT LSTM with packed fma.rn.f32x2 (2 fp32 FMA/inst): thread u owns unit u,
// spans packed pairwise in 64-bit accumulators. h stored [k][span] so the
// k-loop broadcast-loads LDS.64. Double-buffered h, 1 sync/step,
// length-paired sorted groups.
// ---------------------------------------------------------------------------
__device__ __forceinline__ float fast_sig(float x)  { return 1.f / (1.f + __expf(-x)); }
__device__ __forceinline__ float fast_tanh(float x) {
    float t = __expf(-2.f * x);
    return __fdividef(1.f - t, 1.f + t);
}

__global__ __launch_bounds__(224) void lstm_kernel(const int* __restrict__ span_lens) {
    __shared__ float h_sh[2][H_ * HPITCH];   // [buf][k*HPITCH + span]
    __shared__ int   sp_sh[PSPAN];
    __shared__ int   len_sh[PSPAN];

    int tid = threadIdx.x;
    int dir = blockIdx.y;
    int u   = tid;
    bool act = u < H_;

    const float*  Zd = g_Z[dir];
    const float4* Wp = g_Wp[dir];

    for (int phase = 0; phase < 2; phase++) {
        int grp = phase ? (127 - (int)blockIdx.x) : (int)blockIdx.x;
        int n0  = grp * PSPAN;

        __syncthreads();
        if (tid < PSPAN) {
            int sp = g_order[n0 + tid];
            sp_sh[tid]  = sp;
            len_sh[tid] = min(max(span_lens[sp], 0), T_);
        }
        for (int i = tid; i < 2 * H_ * HPITCH; i += 224)
            ((float*)h_sh)[i] = 0.f;
        __syncthreads();

        int maxL = 0;
#pragma unroll
        for (int p = 0; p < PSPAN; p++) maxL = max(maxL, len_sh[p]);

        float c[PSPAN], feat[PSPAN], hreg[PSPAN];
#pragma unroll
        for (int p = 0; p < PSPAN; p++) { c[p] = 0.f; feat[p] = 0.f; hreg[p] = 0.f; }

        int buf = 0;
        for (int s = 0; s < maxL; s++) {
            ull a0[4], a1[4], a2[4], a3[4];
            if (act) {
                float z0[PSPAN], z1[PSPAN], z2[PSPAN], z3[PSPAN];
#pragma unroll
                for (int p = 0; p < PSPAN; p++) {
                    int L = len_sh[p];
                    int t = dir ? (L - 1 - s) : s;
                    if (s >= L) t = 0;
                    const float* z = Zd + ((size_t)sp_sh[p] * T_ + t) * G4H;
                    z0[p] = z[u];
                    z1[p] = z[H_ + u];
                    z2[p] = z[2 * H_ + u];
                    z3[p] = z[3 * H_ + u];
                }
#pragma unroll
                for (int j = 0; j < 4; j++) {
                    a0[j] = pack_f2(z0[2 * j], z0[2 * j + 1]);
                    a1[j] = pack_f2(z1[2 * j], z1[2 * j + 1]);
                    a2[j] = pack_f2(z2[2 * j], z2[2 * j + 1]);
                    a3[j] = pack_f2(z3[2 * j], z3[2 * j + 1]);
                }
                const float* hb = h_sh[buf];
#pragma unroll 2
                for (int k = 0; k < H_; k++) {
                    float4 w = Wp[k * H_ + u];
                    ull w0 = pack_f2(w.x, w.x);
                    ull w1 = pack_f2(w.y, w.y);
                    ull w2 = pack_f2(w.z, w.z);
                    ull w3 = pack_f2(w.w, w.w);
                    const ull* hp = (const ull*)&hb[k * HPITCH];
#pragma unroll
                    for (int j = 0; j < 4; j++) {
                        ull hv = hp[j];
                        FMA_X2(a0[j], w0, hv);
                        FMA_X2(a1[j], w1, hv);
                        FMA_X2(a2[j], w2, hv);
                        FMA_X2(a3[j], w3, hv);
                    }
                }
                float b0[PSPAN], b1[PSPAN], b2[PSPAN], b3[PSPAN];
#pragma unroll
                for (int j = 0; j < 4; j++) {
                    unpack_f2(a0[j], b0[2 * j], b0[2 * j + 1]);
                    unpack_f2(a1[j], b1[2 * j], b1[2 * j + 1]);
                    unpack_f2(a2[j], b2[2 * j], b2[2 * j + 1]);
                    unpack_f2(a3[j], b3[2 * j], b3[2 * j + 1]);
                }
                float* hn_row = &h_sh[buf ^ 1][u * HPITCH];
#pragma unroll
                for (int p = 0; p < PSPAN; p++) {
                    if (s < len_sh[p]) {
                        float ig = fast_sig(b0[p]);
                        float fg = fast_sig(b1[p]);
                        float gg = fast_tanh(b2[p]);
                        float og = fast_sig(b3[p]);
                        float cn = fg * c[p] + ig * gg;
                        c[p] = cn;
                        hreg[p] = og * fast_tanh(cn);
                        feat[p] += hreg[p];
                    }
                    hn_row[p] = hreg[p];
                }
            }
            __syncthreads();
            buf ^= 1;
        }

        if (act) {
#pragma unroll
            for (int p = 0; p < PSPAN; p++)
                g_feats[(size_t)sp_sh[p] * (2 * H_) + dir * H_ + u] = feat[p];
        }
    }
}

// ---------------------------------------------------------------------------
// logits
// ---------------------------------------------------------------------------
__global__ __launch_bounds__(192) void logits_kernel(const float* __restrict__ slot_embs,
                                                     const float* __restrict__ slot_mask,
                                                     float* __restrict__ out) {
    __shared__ float f_sm[16][2 * H_];
    __shared__ float se_sm[2 * H_ * NS_];

    int tid = threadIdx.x;
    int n0  = blockIdx.x * 16;

    for (int i = tid; i < 2 * H_ * NS_; i += blockDim.x) se_sm[i] = slot_embs[i];
    for (int i = tid; i < 16 * 2 * H_; i += blockDim.x) {
        int sp = i / (2 * H_), h = i % (2 * H_);
        f_sm[sp][h] = g_feats[(size_t)(n0 + sp) * (2 * H_) + h];
    }
    __syncthreads();

    int sp = tid / NS_, ns = tid % NS_;
    float acc = 0.f;
#pragma unroll 8
    for (int h = 0; h < 2 * H_; h++) acc += f_sm[sp][h] * se_sm[h * NS_ + ns];
    out[(n0 + sp) * NS_ + ns] = acc * slot_mask[n0 + sp];
}

// ---------------------------------------------------------------------------
extern "C" void kernel_launch(void* const* d_in, const int* in_sizes, int n_in,
                              void* d_out, int out_size) {
    const float* hidden    = (const float*)d_in[0];
    const float* Wih_f     = (const float*)d_in[1];
    const float* Whh_f     = (const float*)d_in[2];
    const float* bih_f     = (const float*)d_in[3];
    const float* bhh_f     = (const float*)d_in[4];
    const float* Wih_b     = (const float*)d_in[5];
    const float* Whh_b     = (const float*)d_in[6];
    const float* bih_b     = (const float*)d_in[7];
    const float* bhh_b     = (const float*)d_in[8];
    const float* slot_embs = (const float*)d_in[9];
    const int*   starts    = (const int*)d_in[10];
    const int*   lens      = (const int*)d_in[11];
    const float* slot_mask = (const float*)d_in[12];
    float* out = (float*)d_out;

    const int gemm_smem = 2 * STG * (int)sizeof(unsigned);   // 73728 B
    cudaFuncSetAttribute(gemm_tc, cudaFuncAttributeMaxDynamicSharedMemorySize, gemm_smem);

    pack_kernel<<<1024, 256>>>(Wih_f, Whh_f, bih_f, bhh_f,
                               Wih_b, Whh_b, bih_b, bhh_b);
    prep_kernel<<<1, NSPAN>>>(lens);

    gather_split<<<(MROWS * (KP / 8) + 255) / 256, 256>>>(hidden, starts);

    dim3 ggrid(NCPAD / 128, MROWS / 128);
    gemm_tc<<<ggrid, 256, gemm_smem>>>();

    dim3 lgrid(64, 2);
    lstm_kernel<<<lgrid, 224>>>(lens);

    logits_kernel<<<NSPAN / 16, 192>>>(slot_embs, slot_mask, out);
}

// round 8
// speedup vs baseline: 1.5304x; 1.1683x over previous
#include <cuda_runtime.h>
#include <cuda_fp16.h>
#include <math.h>

#define B_    64
#define S_    1024
#define D_    800
#define MS_   16
#define T_    32
#define H_    200
#define NS_   12
#define NSPAN (B_*MS_)        // 1024
#define MROWS (NSPAN*T_)      // 32768
#define KDIM  D_              // 800
#define KP    832             // GEMM K padded (52 k-slices of 16)
#define KP2   (KP/2)          // 416 u32 per row
#define NSLICE (KP/16)        // 52
#define G4H   (4*H_)          // 800
#define NCOLS 1600
#define NCPAD 1664
#define PSPAN 8
#define KC    64
#define KC2   (KC/2)
#define PITCH 40              // GEMM smem pitch (u32): LDS.64 conflict-free

typedef unsigned long long ull;

// -------- scratch (static device arrays; no runtime alloc) ------------------
__device__ float    g_Z[2][(size_t)MROWS * G4H];
__device__ unsigned g_A16[(size_t)MROWS * KP2];    // gathered A fp16, slice-interleaved
__device__ unsigned g_B16[(size_t)NCPAD * KP2];    // Wih^T n-major fp16, slice-interleaved
__device__ float4   g_Wp[2][H_ * H_];              // recurrent weights [dir][k*H+u]
__device__ float    g_biasC[NCPAD];
__device__ float    g_feats[(size_t)NSPAN * 2 * H_];
__device__ int      g_rows[MROWS];
__device__ int      g_order[NSPAN];
__device__ int      g_cnt;

__device__ __forceinline__ unsigned pack_h2(float x0, float x1) {
    __half2 h = __floats2half2_rn(x0, x1);
    return *reinterpret_cast<unsigned*>(&h);
}

// slice interleave: slot 2t = kpair t, slot 2t+1 = kpair t+4  (t = 0..3)
// -> LDS.64 at slot 2*tg yields (kpair tg, kpair tg+4), the mma frag pair.

// ---------------------------------------------------------------------------
// Pack: Wih^T -> n-major fp16 (slice-interleaved); gate-pack Whh; biases.
// One thread = one 16-k slice of one column.
// ---------------------------------------------------------------------------
__global__ void pack_kernel(const float* __restrict__ Wih_f, const float* __restrict__ Whh_f,
                            const float* __restrict__ bih_f, const float* __restrict__ bhh_f,
                            const float* __restrict__ Wih_b, const float* __restrict__ Whh_b,
                            const float* __restrict__ bih_b, const float* __restrict__ bhh_b) {
    int stride = gridDim.x * blockDim.x;
    int tid0   = blockIdx.x * blockDim.x + threadIdx.x;

    for (int idx = tid0; idx < NCPAD * NSLICE; idx += stride) {
        int j = idx / NSLICE, ks = idx % NSLICE;
        int k0 = ks * 16;
        float xs[16];
#pragma unroll
        for (int e = 0; e < 16; e++) {
            int k = k0 + e;
            float v = 0.f;
            if (j < NCOLS && k < KDIM)
                v = (j < G4H) ? Wih_f[(size_t)j * D_ + k]
                              : Wih_b[(size_t)(j - G4H) * D_ + k];
            xs[e] = v;
        }
        unsigned slots[8];
#pragma unroll
        for (int t = 0; t < 4; t++) {
            slots[2 * t]     = pack_h2(xs[2 * t],     xs[2 * t + 1]);       // kpair t
            slots[2 * t + 1] = pack_h2(xs[2 * t + 8], xs[2 * t + 9]);       // kpair t+4
        }
        unsigned* dst = &g_B16[(size_t)j * KP2 + ks * 8];
        *reinterpret_cast<uint4*>(dst)     = *reinterpret_cast<uint4*>(&slots[0]);
        *reinterpret_cast<uint4*>(dst + 4) = *reinterpret_cast<uint4*>(&slots[4]);
    }
    for (int idx = tid0; idx < 2 * H_ * H_; idx += stride) {
        int dir = idx / (H_ * H_);
        int rem = idx % (H_ * H_);
        int k = rem / H_, u = rem % H_;
        const float* Whh = dir ? Whh_b : Whh_f;
        float4 v;
        v.x = Whh[(size_t)(0 * H_ + u) * H_ + k];
        v.y = Whh[(size_t)(1 * H_ + u) * H_ + k];
        v.z = Whh[(size_t)(2 * H_ + u) * H_ + k];
        v.w = Whh[(size_t)(3 * H_ + u) * H_ + k];
        g_Wp[dir][k * H_ + u] = v;
    }
    for (int idx = tid0; idx < NCPAD; idx += stride) {
        float v = 0.f;
        if (idx < NCOLS) {
            int dir = idx / G4H, jj = idx % G4H;
            v = dir ? (bih_b[jj] + bhh_b[jj]) : (bih_f[jj] + bhh_f[jj]);
        }
        g_biasC[idx] = v;
    }
}

// ---------------------------------------------------------------------------
// Prep: prefix-scan lens -> compacted rows; parallel stable counting sort.
// ---------------------------------------------------------------------------
__global__ void prep_kernel(const int* __restrict__ lens) {
    __shared__ int s[NSPAN];
    __shared__ int wcnt[32][T_ + 1];
    __shared__ int st[T_ + 1];
    __shared__ int tot[T_ + 1];
    int tid = threadIdx.x;
    int lane = tid & 31, w = tid >> 5;
    int l = min(max(lens[tid], 0), T_);
    s[tid] = l;
    for (int b = lane; b <= T_; b += 32) wcnt[w][b] = 0;
    __syncthreads();
    for (int d = 1; d < NSPAN; d <<= 1) {
        int v = (tid >= d) ? s[tid - d] : 0;
        __syncthreads();
        s[tid] += v;
        __syncthreads();
    }
    int off = s[tid] - l;
    for (int t = 0; t < l; t++) g_rows[off + t] = tid * T_ + t;
    if (tid == NSPAN - 1) g_cnt = s[tid];

    unsigned mask = __match_any_sync(0xffffffffu, l);
    int rin = __popc(mask & ((1u << lane) - 1u));
    if (rin == 0) wcnt[w][l] = __popc(mask);
    __syncthreads();
    if (tid <= T_) {
        int acc = 0;
        for (int ww = 0; ww < 32; ww++) {
            int c = wcnt[ww][tid];
            wcnt[ww][tid] = acc;
            acc += c;
        }
        tot[tid] = acc;
    }
    __syncthreads();
    if (tid == 0) {
        int a = 0;
        for (int b = 0; b <= T_; b++) { st[b] = a; a += tot[b]; }
    }
    __syncthreads();
    g_order[st[l] + wcnt[w][l] + rin] = tid;
}

// ---------------------------------------------------------------------------
// Gather A -> fp16, slice-interleaved. One thread = one 16-k slice of one row.
// ---------------------------------------------------------------------------
__global__ void gather_split(const float* __restrict__ hidden,
                             const int*   __restrict__ starts) {
    int idx = blockIdx.x * blockDim.x + threadIdx.x;
    int total = g_cnt * NSLICE;
    if (idx >= total) return;
    int m = idx / NSLICE, ks = idx % NSLICE;
    int k0 = ks * 16;
    float xs[16];
    if (k0 < KDIM) {
        int r = g_rows[m];
        int sp = r >> 5, t = r & 31;
        int b = sp >> 4, mm = sp & 15;
        int src = min(max(starts[b * MS_ + mm] + t, 0), S_ - 1);
        const float* base = &hidden[((size_t)b * S_ + src) * D_ + k0];
#pragma unroll
        for (int e = 0; e < 4; e++) {
            float4 v = *reinterpret_cast<const float4*>(base + 4 * e);
            xs[4 * e + 0] = v.x; xs[4 * e + 1] = v.y;
            xs[4 * e + 2] = v.z; xs[4 * e + 3] = v.w;
        }
    } else {
#pragma unroll
        for (int e = 0; e < 16; e++) xs[e] = 0.f;
    }
    unsigned slots[8];
#pragma unroll
    for (int t = 0; t < 4; t++) {
        slots[2 * t]     = pack_h2(xs[2 * t],     xs[2 * t + 1]);
        slots[2 * t + 1] = pack_h2(xs[2 * t + 8], xs[2 * t + 9]);
    }
    unsigned* dst = &g_A16[(size_t)m * KP2 + ks * 8];
    *reinterpret_cast<uint4*>(dst)     = *reinterpret_cast<uint4*>(&slots[0]);
    *reinterpret_cast<uint4*>(dst + 4) = *reinterpret_cast<uint4*>(&slots[4]);
}

// ---------------------------------------------------------------------------
// fp16 GEMM, cp.async double-buffered, LDS.64 fragment loads.
// ---------------------------------------------------------------------------
#define MMA_FP16(d, a, b)                                                       \
    asm volatile("mma.sync.aligned.m16n8k16.row.col.f32.f16.f16.f32 "           \
                 "{%0,%1,%2,%3}, {%4,%5,%6,%7}, {%8,%9}, {%0,%1,%2,%3};"        \
                 : "+f"(d[0]), "+f"(d[1]), "+f"(d[2]), "+f"(d[3])               \
                 : "r"(a[0]), "r"(a[1]), "r"(a[2]), "r"(a[3]),                  \
                   "r"(b[0]), "r"(b[1]));

__device__ __forceinline__ void cp16(unsigned* smem_ptr, const unsigned* gptr) {
    unsigned saddr = (unsigned)__cvta_generic_to_shared(smem_ptr);
    asm volatile("cp.async.cg.shared.global [%0], [%1], 16;" :: "r"(saddr), "l"(gptr));
}

#define MAT_TILE (128 * PITCH)          // 5120 u32
#define STG      (2 * MAT_TILE)         // 10240 u32/stage (40KB)

extern __shared__ unsigned smem_u[];

__global__ __launch_bounds__(256, 2) void gemm_tc(void) {
    const int cnt = g_cnt;
    const int m0  = blockIdx.y * 128;
    if (m0 >= cnt) return;
    const int n0  = blockIdx.x * 128;

    __shared__ int rowIdx[128];
    int tid = threadIdx.x;
    if (tid < 128) {
        int m = m0 + tid;
        rowIdx[tid] = (m < cnt) ? g_rows[m] : -1;
    }

    float acc[16][4];
#pragma unroll
    for (int i = 0; i < 16; i++)
#pragma unroll
        for (int q = 0; q < 4; q++) acc[i][q] = 0.f;

    int lane = tid & 31, wid = tid >> 5;
    int wm = wid >> 2, wn = wid & 3;
    int g = lane >> 2, tg = lane & 3;

    auto load_stage = [&](int stage, int k0u) {
        unsigned* As = smem_u + stage * STG;
        unsigned* Bs = As + MAT_TILE;
#pragma unroll
        for (int i = 0; i < 4; i++) {
            int id = tid + i * 256;
            int m = id >> 3, c = id & 7;   // 128 rows x 8 chunks of 4 u32
            cp16(&As[m * PITCH + c * 4], &g_A16[(size_t)(m0 + m) * KP2 + k0u + c * 4]);
        }
#pragma unroll
        for (int i = 0; i < 4; i++) {
            int id = tid + i * 256;
            int n = id >> 3, c = id & 7;
            cp16(&Bs[n * PITCH + c * 4], &g_B16[(size_t)(n0 + n) * KP2 + k0u + c * 4]);
        }
    };

    const int NITER = KP / KC;   // 13
    load_stage(0, 0);
    asm volatile("cp.async.commit_group;");

    for (int it = 0; it < NITER; it++) {
        if (it + 1 < NITER) load_stage((it + 1) & 1, (it + 1) * KC2);
        asm volatile("cp.async.commit_group;");
        asm volatile("cp.async.wait_group 1;");
        __syncthreads();

        const unsigned* As = smem_u + (it & 1) * STG;
        const unsigned* Bs = As + MAT_TILE;

#pragma unroll
        for (int ks = 0; ks < 4; ks++) {
            int kp = ks * 8;
            unsigned af[4][4];
#pragma unroll
            for (int mt = 0; mt < 4; mt++) {
                int r0 = wm * 64 + mt * 16 + g;
                ull v0 = *reinterpret_cast<const ull*>(As + r0 * PITCH + kp + 2 * tg);
                ull v1 = *reinterpret_cast<const ull*>(As + (r0 + 8) * PITCH + kp + 2 * tg);
                af[mt][0] = (unsigned)v0;          // row g,   kpair tg
                af[mt][2] = (unsigned)(v0 >> 32);  // row g,   kpair tg+4
                af[mt][1] = (unsigned)v1;          // row g+8, kpair tg
                af[mt][3] = (unsigned)(v1 >> 32);  // row g+8, kpair tg+4
            }
            unsigned bf[4][2];
#pragma unroll
            for (int nt = 0; nt < 4; nt++) {
                int c = wn * 32 + nt * 8 + g;
                ull v = *reinterpret_cast<const ull*>(Bs + c * PITCH + kp + 2 * tg);
                bf[nt][0] = (unsigned)v;
                bf[nt][1] = (unsigned)(v >> 32);
            }
#pragma unroll
            for (int mt = 0; mt < 4; mt++)
#pragma unroll
                for (int nt = 0; nt < 4; nt++)
                    MMA_FP16(acc[mt * 4 + nt], af[mt], bf[nt]);
        }
        __syncthreads();
    }

#pragma unroll
    for (int mt = 0; mt < 4; mt++) {
        int lr0 = wm * 64 + mt * 16 + g;
#pragma unroll
        for (int nt = 0; nt < 4; nt++) {
            int c = n0 + wn * 32 + nt * 8 + tg * 2;
            if (c >= NCOLS) continue;
            float* a = acc[mt * 4 + nt];
            float2 bias = *reinterpret_cast<const float2*>(&g_biasC[c]);
            int dirb = (c >= G4H);
            int cc   = dirb ? (c - G4H) : c;
#pragma unroll
            for (int h = 0; h < 2; h++) {
                int lr = lr0 + h * 8;
                if (m0 + lr < cnt) {
                    float2 v;
                    v.x = a[h * 2 + 0] + bias.x;
                    v.y = a[h * 2 + 1] + bias.y;
                    int rid = rowIdx[lr];
                    *reinterpret_cast<float2*>(&g_Z[dirb][(size_t)rid * G4H + cc]) = v;
                }
            }
        }
    }
}

// ---------------------------------------------------------------------------
// Recurrence: EXACT round-5 kernel (known-good ~455us). Thread u owns unit u,
// double-buffered h in smem, float4 k-vectorization, length-paired groups.
// ---------------------------------------------------------------------------
__device__ __forceinline__ float fast_sig(float x)  { return 1.f / (1.f + __expf(-x)); }
__device__ __forceinline__ float fast_tanh(float x) {
    float t = __expf(-2.f * x);
    return __fdividef(1.f - t, 1.f + t);
}

__global__ __launch_bounds__(224) void lstm_kernel(const int* __restrict__ span_lens) {
    __shared__ float4 h4[2][PSPAN][H_ / 4];
    __shared__ int    sp_sh[PSPAN];
    __shared__ int    len_sh[PSPAN];

    int tid = threadIdx.x;
    int dir = blockIdx.y;
    int u   = tid;
    bool act = u < H_;

    const float*  Zd = g_Z[dir];
    const float4* Wp = g_Wp[dir];

    for (int phase = 0; phase < 2; phase++) {
        int grp = phase ? (127 - (int)blockIdx.x) : (int)blockIdx.x;
        int n0  = grp * PSPAN;

        __syncthreads();
        if (tid < PSPAN) {
            int sp = g_order[n0 + tid];
            sp_sh[tid]  = sp;
            len_sh[tid] = min(max(span_lens[sp], 0), T_);
        }
        {
            float* hz = (float*)h4;
            for (int i = tid; i < PSPAN * H_; i += 224) hz[i] = 0.f;
        }
        __syncthreads();

        int maxL = 0;
#pragma unroll
        for (int p = 0; p < PSPAN; p++) maxL = max(maxL, len_sh[p]);

        float c[PSPAN], feat[PSPAN], hreg[PSPAN];
#pragma unroll
        for (int p = 0; p < PSPAN; p++) { c[p] = 0.f; feat[p] = 0.f; hreg[p] = 0.f; }

        int buf = 0;
        for (int s = 0; s < maxL; s++) {
            float a0[PSPAN], a1[PSPAN], a2[PSPAN], a3[PSPAN];
            if (act) {
#pragma unroll
                for (int p = 0; p < PSPAN; p++) {
                    int L = len_sh[p];
                    int t = dir ? (L - 1 - s) : s;
                    if (s >= L) t = 0;
                    const float* z = Zd + ((size_t)sp_sh[p] * T_ + t) * G4H;
                    a0[p] = z[u];
                    a1[p] = z[H_ + u];
                    a2[p] = z[2 * H_ + u];
                    a3[p] = z[3 * H_ + u];
                }
#pragma unroll 2
                for (int k = 0; k < H_; k += 4) {
                    float4 w0 = Wp[(k + 0) * H_ + u];
                    float4 w1 = Wp[(k + 1) * H_ + u];
                    float4 w2 = Wp[(k + 2) * H_ + u];
                    float4 w3 = Wp[(k + 3) * H_ + u];
#pragma unroll
                    for (int p = 0; p < PSPAN; p++) {
                        float4 hv = h4[buf][p][k >> 2];
                        a0[p] += w0.x * hv.x; a0[p] += w1.x * hv.y;
                        a0[p] += w2.x * hv.z; a0[p] += w3.x * hv.w;
                        a1[p] += w0.y * hv.x; a1[p] += w1.y * hv.y;
                        a1[p] += w2.y * hv.z; a1[p] += w3.y * hv.w;
                        a2[p] += w0.z * hv.x; a2[p] += w1.z * hv.y;
                        a2[p] += w2.z * hv.z; a2[p] += w3.z * hv.w;
                        a3[p] += w0.w * hv.x; a3[p] += w1.w * hv.y;
                        a3[p] += w2.w * hv.z; a3[p] += w3.w * hv.w;
                    }
                }
#pragma unroll
                for (int p = 0; p < PSPAN; p++) {
                    if (s < len_sh[p]) {
                        float ig = fast_sig(a0[p]);
                        float fg = fast_sig(a1[p]);
                        float gg = fast_tanh(a2[p]);
                        float og = fast_sig(a3[p]);
                        float cn = fg * c[p] + ig * gg;
                        c[p] = cn;
                        hreg[p] = og * fast_tanh(cn);
                        feat[p] += hreg[p];
                    }
                    ((float*)&h4[buf ^ 1][p][0])[u] = hreg[p];
                }
            }
            __syncthreads();
            buf ^= 1;
        }

        if (act) {
#pragma unroll
            for (int p = 0; p < PSPAN; p++)
                g_feats[(size_t)sp_sh[p] * (2 * H_) + dir * H_ + u] = feat[p];
        }
    }
}

// ---------------------------------------------------------------------------
// logits
// ---------------------------------------------------------------------------
__global__ __launch_bounds__(192) void logits_kernel(const float* __restrict__ slot_embs,
                                                     const float* __restrict__ slot_mask,
                                                     float* __restrict__ out) {
    __shared__ float f_sm[16][2 * H_];
    __shared__ float se_sm[2 * H_ * NS_];

    int tid = threadIdx.x;
    int n0  = blockIdx.x * 16;

    for (int i = tid; i < 2 * H_ * NS_; i += blockDim.x) se_sm[i] = slot_embs[i];
    for (int i = tid; i < 16 * 2 * H_; i += blockDim.x) {
        int sp = i / (2 * H_), h = i % (2 * H_);
        f_sm[sp][h] = g_feats[(size_t)(n0 + sp) * (2 * H_) + h];
    }
    __syncthreads();

    int sp = tid / NS_, ns = tid % NS_;
    float acc = 0.f;
#pragma unroll 8
    for (int h = 0; h < 2 * H_; h++) acc += f_sm[sp][h] * se_sm[h * NS_ + ns];
    out[(n0 + sp) * NS_ + ns] = acc * slot_mask[n0 + sp];
}

// ---------------------------------------------------------------------------
extern "C" void kernel_launch(void* const* d_in, const int* in_sizes, int n_in,
                              void* d_out, int out_size) {
    const float* hidden    = (const float*)d_in[0];
    const float* Wih_f     = (const float*)d_in[1];
    const float* Whh_f     = (const float*)d_in[2];
    const float* bih_f     = (const float*)d_in[3];
    const float* bhh_f     = (const float*)d_in[4];
    const float* Wih_b     = (const float*)d_in[5];
    const float* Whh_b     = (const float*)d_in[6];
    const float* bih_b     = (const float*)d_in[7];
    const float* bhh_b     = (const float*)d_in[8];
    const float* slot_embs = (const float*)d_in[9];
    const int*   starts    = (const int*)d_in[10];
    const int*   lens      = (const int*)d_in[11];
    const float* slot_mask = (const float*)d_in[12];
    float* out = (float*)d_out;

    const int gemm_smem = 2 * STG * (int)sizeof(unsigned);   // 81920 B
    cudaFuncSetAttribute(gemm_tc, cudaFuncAttributeMaxDynamicSharedMemorySize, gemm_smem);

    pack_kernel<<<1024, 256>>>(Wih_f, Whh_f, bih_f, bhh_f,
                               Wih_b, Whh_b, bih_b, bhh_b);
    prep_kernel<<<1, NSPAN>>>(lens);

    gather_split<<<(MROWS * NSLICE + 255) / 256, 256>>>(hidden, starts);

    dim3 ggrid(NCPAD / 128, MROWS / 128);
    gemm_tc<<<ggrid, 256, gemm_smem>>>();

    dim3 lgrid(64, 2);
    lstm_kernel<<<lgrid, 224>>>(lens);

    logits_kernel<<<NSPAN / 16, 192>>>(slot_embs, slot_mask, out);
}

// round 9
// speedup vs baseline: 1.5799x; 1.0323x over previous
#include <cuda_runtime.h>
#include <cuda_fp16.h>
#include <math.h>

#define B_    64
#define S_    1024
#define D_    800
#define MS_   16
#define T_    32
#define H_    200
#define NS_   12
#define NSPAN (B_*MS_)        // 1024
#define MROWS (NSPAN*T_)      // 32768
#define KDIM  D_              // 800
#define KP    832             // GEMM K padded (52 k-slices of 16)
#define KP2   (KP/2)          // 416 u32 per row
#define NSLICE (KP/16)        // 52
#define G4H   (4*H_)          // 800
#define NCOLS 1600
#define NCPAD 1664
#define PSPAN 8
#define KC    64
#define KC2   (KC/2)
#define PITCH 40              // GEMM smem pitch (u32): LDS.64 conflict-free

typedef unsigned long long ull;

// -------- scratch (static device arrays; no runtime alloc) ------------------
__device__ float    g_Z[2][(size_t)MROWS * G4H];
__device__ unsigned g_A16[(size_t)MROWS * KP2];    // gathered A fp16, slice-interleaved
__device__ unsigned g_B16[(size_t)NCPAD * KP2];    // Wih^T n-major fp16, slice-interleaved
__device__ float4   g_Wp[2][H_ * H_];              // recurrent weights [dir][k*H+u]
__device__ float    g_biasC[NCPAD];
__device__ float    g_feats[(size_t)NSPAN * 2 * H_];
__device__ int      g_rows[MROWS];
__device__ int      g_order[NSPAN];
__device__ int      g_cnt;

__device__ __forceinline__ unsigned pack_h2(float x0, float x1) {
    __half2 h = __floats2half2_rn(x0, x1);
    return *reinterpret_cast<unsigned*>(&h);
}

// slice interleave: slot 2t = kpair t, slot 2t+1 = kpair t+4  (t = 0..3)
// -> LDS.64 at slot 2*tg yields (kpair tg, kpair tg+4), the mma frag pair.

// ---------------------------------------------------------------------------
// Pack: Wih^T -> n-major fp16 (slice-interleaved); gate-pack Whh; biases.
// ---------------------------------------------------------------------------
__global__ void pack_kernel(const float* __restrict__ Wih_f, const float* __restrict__ Whh_f,
                            const float* __restrict__ bih_f, const float* __restrict__ bhh_f,
                            const float* __restrict__ Wih_b, const float* __restrict__ Whh_b,
                            const float* __restrict__ bih_b, const float* __restrict__ bhh_b) {
    int stride = gridDim.x * blockDim.x;
    int tid0   = blockIdx.x * blockDim.x + threadIdx.x;

    for (int idx = tid0; idx < NCPAD * NSLICE; idx += stride) {
        int j = idx / NSLICE, ks = idx % NSLICE;
        int k0 = ks * 16;
        float xs[16];
#pragma unroll
        for (int e = 0; e < 16; e++) {
            int k = k0 + e;
            float v = 0.f;
            if (j < NCOLS && k < KDIM)
                v = (j < G4H) ? Wih_f[(size_t)j * D_ + k]
                              : Wih_b[(size_t)(j - G4H) * D_ + k];
            xs[e] = v;
        }
        unsigned slots[8];
#pragma unroll
        for (int t = 0; t < 4; t++) {
            slots[2 * t]     = pack_h2(xs[2 * t],     xs[2 * t + 1]);       // kpair t
            slots[2 * t + 1] = pack_h2(xs[2 * t + 8], xs[2 * t + 9]);       // kpair t+4
        }
        unsigned* dst = &g_B16[(size_t)j * KP2 + ks * 8];
        *reinterpret_cast<uint4*>(dst)     = *reinterpret_cast<uint4*>(&slots[0]);
        *reinterpret_cast<uint4*>(dst + 4) = *reinterpret_cast<uint4*>(&slots[4]);
    }
    for (int idx = tid0; idx < 2 * H_ * H_; idx += stride) {
        int dir = idx / (H_ * H_);
        int rem = idx % (H_ * H_);
        int k = rem / H_, u = rem % H_;
        const float* Whh = dir ? Whh_b : Whh_f;
        float4 v;
        v.x = Whh[(size_t)(0 * H_ + u) * H_ + k];
        v.y = Whh[(size_t)(1 * H_ + u) * H_ + k];
        v.z = Whh[(size_t)(2 * H_ + u) * H_ + k];
        v.w = Whh[(size_t)(3 * H_ + u) * H_ + k];
        g_Wp[dir][k * H_ + u] = v;
    }
    for (int idx = tid0; idx < NCPAD; idx += stride) {
        float v = 0.f;
        if (idx < NCOLS) {
            int dir = idx / G4H, jj = idx % G4H;
            v = dir ? (bih_b[jj] + bhh_b[jj]) : (bih_f[jj] + bhh_f[jj]);
        }
        g_biasC[idx] = v;
    }
}

// ---------------------------------------------------------------------------
// Prep: prefix-scan lens -> compacted rows; parallel counting sort, spans
// ordered by DESCENDING length (greedy CTA-scheduler packing for the LSTM).
// ---------------------------------------------------------------------------
__global__ void prep_kernel(const int* __restrict__ lens) {
    __shared__ int s[NSPAN];
    __shared__ int wcnt[32][T_ + 1];
    __shared__ int st[T_ + 1];
    __shared__ int tot[T_ + 1];
    int tid = threadIdx.x;
    int lane = tid & 31, w = tid >> 5;
    int l = min(max(lens[tid], 0), T_);
    s[tid] = l;
    for (int b = lane; b <= T_; b += 32) wcnt[w][b] = 0;
    __syncthreads();
    for (int d = 1; d < NSPAN; d <<= 1) {
        int v = (tid >= d) ? s[tid - d] : 0;
        __syncthreads();
        s[tid] += v;
        __syncthreads();
    }
    int off = s[tid] - l;
    for (int t = 0; t < l; t++) g_rows[off + t] = tid * T_ + t;
    if (tid == NSPAN - 1) g_cnt = s[tid];

    unsigned mask = __match_any_sync(0xffffffffu, l);
    int rin = __popc(mask & ((1u << lane) - 1u));
    if (rin == 0) wcnt[w][l] = __popc(mask);
    __syncthreads();
    if (tid <= T_) {
        int acc = 0;
        for (int ww = 0; ww < 32; ww++) {
            int c = wcnt[ww][tid];
            wcnt[ww][tid] = acc;
            acc += c;
        }
        tot[tid] = acc;
    }
    __syncthreads();
    if (tid == 0) {
        int a = 0;
        for (int b = T_; b >= 0; b--) { st[b] = a; a += tot[b]; }   // descending
    }
    __syncthreads();
    g_order[st[l] + wcnt[w][l] + rin] = tid;
}

// ---------------------------------------------------------------------------
// Gather A -> fp16, slice-interleaved.
// ---------------------------------------------------------------------------
__global__ void gather_split(const float* __restrict__ hidden,
                             const int*   __restrict__ starts) {
    int idx = blockIdx.x * blockDim.x + threadIdx.x;
    int total = g_cnt * NSLICE;
    if (idx >= total) return;
    int m = idx / NSLICE, ks = idx % NSLICE;
    int k0 = ks * 16;
    float xs[16];
    if (k0 < KDIM) {
        int r = g_rows[m];
        int sp = r >> 5, t = r & 31;
        int b = sp >> 4, mm = sp & 15;
        int src = min(max(starts[b * MS_ + mm] + t, 0), S_ - 1);
        const float* base = &hidden[((size_t)b * S_ + src) * D_ + k0];
#pragma unroll
        for (int e = 0; e < 4; e++) {
            float4 v = *reinterpret_cast<const float4*>(base + 4 * e);
            xs[4 * e + 0] = v.x; xs[4 * e + 1] = v.y;
            xs[4 * e + 2] = v.z; xs[4 * e + 3] = v.w;
        }
    } else {
#pragma unroll
        for (int e = 0; e < 16; e++) xs[e] = 0.f;
    }
    unsigned slots[8];
#pragma unroll
    for (int t = 0; t < 4; t++) {
        slots[2 * t]     = pack_h2(xs[2 * t],     xs[2 * t + 1]);
        slots[2 * t + 1] = pack_h2(xs[2 * t + 8], xs[2 * t + 9]);
    }
    unsigned* dst = &g_A16[(size_t)m * KP2 + ks * 8];
    *reinterpret_cast<uint4*>(dst)     = *reinterpret_cast<uint4*>(&slots[0]);
    *reinterpret_cast<uint4*>(dst + 4) = *reinterpret_cast<uint4*>(&slots[4]);
}

// ---------------------------------------------------------------------------
// fp16 GEMM: 4 warps, warp tile 64x64 (2x2 warp grid) -> halves smem crossbar
// traffic per mma (the round-8 binding constraint). cp.async double-buffered.
// ---------------------------------------------------------------------------
#define MMA_FP16(d, a, b)                                                       \
    asm volatile("mma.sync.aligned.m16n8k16.row.col.f32.f16.f16.f32 "           \
                 "{%0,%1,%2,%3}, {%4,%5,%6,%7}, {%8,%9}, {%0,%1,%2,%3};"        \
                 : "+f"(d[0]), "+f"(d[1]), "+f"(d[2]), "+f"(d[3])               \
                 : "r"(a[0]), "r"(a[1]), "r"(a[2]), "r"(a[3]),                  \
                   "r"(b[0]), "r"(b[1]));

__device__ __forceinline__ void cp16(unsigned* smem_ptr, const unsigned* gptr) {
    unsigned saddr = (unsigned)__cvta_generic_to_shared(smem_ptr);
    asm volatile("cp.async.cg.shared.global [%0], [%1], 16;" :: "r"(saddr), "l"(gptr));
}

#define MAT_TILE (128 * PITCH)          // 5120 u32
#define STG      (2 * MAT_TILE)         // 10240 u32/stage (40KB)

extern __shared__ unsigned smem_u[];

__global__ __launch_bounds__(128, 2) void gemm_tc(void) {
    const int cnt = g_cnt;
    const int m0  = blockIdx.y * 128;
    if (m0 >= cnt) return;
    const int n0  = blockIdx.x * 128;

    __shared__ int rowIdx[128];
    int tid = threadIdx.x;
    rowIdx[tid] = (m0 + tid < cnt) ? g_rows[m0 + tid] : -1;

    float acc[32][4];                     // mt(4) x nt(8)
#pragma unroll
    for (int i = 0; i < 32; i++)
#pragma unroll
        for (int q = 0; q < 4; q++) acc[i][q] = 0.f;

    int lane = tid & 31, wid = tid >> 5;  // 4 warps
    int wm = wid >> 1, wn = wid & 1;      // 2x2 warp grid
    int g = lane >> 2, tg = lane & 3;

    auto load_stage = [&](int stage, int k0u) {
        unsigned* As = smem_u + stage * STG;
        unsigned* Bs = As + MAT_TILE;
#pragma unroll
        for (int i = 0; i < 8; i++) {
            int id = tid + i * 128;
            int m = id >> 3, c = id & 7;   // 128 rows x 8 chunks of 4 u32
            cp16(&As[m * PITCH + c * 4], &g_A16[(size_t)(m0 + m) * KP2 + k0u + c * 4]);
        }
#pragma unroll
        for (int i = 0; i < 8; i++) {
            int id = tid + i * 128;
            int n = id >> 3, c = id & 7;
            cp16(&Bs[n * PITCH + c * 4], &g_B16[(size_t)(n0 + n) * KP2 + k0u + c * 4]);
        }
    };

    const int NITER = KP / KC;   // 13
    load_stage(0, 0);
    asm volatile("cp.async.commit_group;");

    for (int it = 0; it < NITER; it++) {
        if (it + 1 < NITER) load_stage((it + 1) & 1, (it + 1) * KC2);
        asm volatile("cp.async.commit_group;");
        asm volatile("cp.async.wait_group 1;");
        __syncthreads();

        const unsigned* As = smem_u + (it & 1) * STG;
        const unsigned* Bs = As + MAT_TILE;

#pragma unroll
        for (int ks = 0; ks < 4; ks++) {
            int kp = ks * 8;
            unsigned af[4][4];
#pragma unroll
            for (int mt = 0; mt < 4; mt++) {
                int r0 = wm * 64 + mt * 16 + g;
                ull v0 = *reinterpret_cast<const ull*>(As + r0 * PITCH + kp + 2 * tg);
                ull v1 = *reinterpret_cast<const ull*>(As + (r0 + 8) * PITCH + kp + 2 * tg);
                af[mt][0] = (unsigned)v0;          // row g,   kpair tg
                af[mt][2] = (unsigned)(v0 >> 32);  // row g,   kpair tg+4
                af[mt][1] = (unsigned)v1;          // row g+8, kpair tg
                af[mt][3] = (unsigned)(v1 >> 32);  // row g+8, kpair tg+4
            }
            unsigned bf[8][2];
#pragma unroll
            for (int nt = 0; nt < 8; nt++) {
                int c = wn * 64 + nt * 8 + g;
                ull v = *reinterpret_cast<const ull*>(Bs + c * PITCH + kp + 2 * tg);
                bf[nt][0] = (unsigned)v;
                bf[nt][1] = (unsigned)(v >> 32);
            }
#pragma unroll
            for (int mt = 0; mt < 4; mt++)
#pragma unroll
                for (int nt = 0; nt < 8; nt++)
                    MMA_FP16(acc[mt * 8 + nt], af[mt], bf[nt]);
        }
        __syncthreads();
    }

#pragma unroll
    for (int mt = 0; mt < 4; mt++) {
        int lr0 = wm * 64 + mt * 16 + g;
#pragma unroll
        for (int nt = 0; nt < 8; nt++) {
            int c = n0 + wn * 64 + nt * 8 + tg * 2;
            if (c >= NCOLS) continue;
            float* a = acc[mt * 8 + nt];
            float2 bias = *reinterpret_cast<const float2*>(&g_biasC[c]);
            int dirb = (c >= G4H);
            int cc   = dirb ? (c - G4H) : c;
#pragma unroll
            for (int h = 0; h < 2; h++) {
                int lr = lr0 + h * 8;
                if (m0 + lr < cnt) {
                    float2 v;
                    v.x = a[h * 2 + 0] + bias.x;
                    v.y = a[h * 2 + 1] + bias.y;
                    int rid = rowIdx[lr];
                    *reinterpret_cast<float2*>(&g_Z[dirb][(size_t)rid * G4H + cc]) = v;
                }
            }
        }
    }
}

// ---------------------------------------------------------------------------
// Recurrence: round-5 body, but ONE group per CTA, grid (128, 2) = 256 CTAs,
// groups sorted by descending length -> greedy scheduler load-balancing.
// ---------------------------------------------------------------------------
__device__ __forceinline__ float fast_sig(float x)  { return 1.f / (1.f + __expf(-x)); }
__device__ __forceinline__ float fast_tanh(float x) {
    float t = __expf(-2.f * x);
    return __fdividef(1.f - t, 1.f + t);
}

__global__ __launch_bounds__(224) void lstm_kernel(const int* __restrict__ span_lens) {
    __shared__ float4 h4[2][PSPAN][H_ / 4];
    __shared__ int    sp_sh[PSPAN];
    __shared__ int    len_sh[PSPAN];

    int tid = threadIdx.x;
    int dir = blockIdx.y;
    int u   = tid;
    bool act = u < H_;
    int n0  = blockIdx.x * PSPAN;

    const float*  Zd = g_Z[dir];
    const float4* Wp = g_Wp[dir];

    if (tid < PSPAN) {
        int sp = g_order[n0 + tid];
        sp_sh[tid]  = sp;
        len_sh[tid] = min(max(span_lens[sp], 0), T_);
    }
    {
        float* hz = (float*)h4;
        for (int i = tid; i < PSPAN * H_; i += 224) hz[i] = 0.f;
    }
    __syncthreads();

    int maxL = 0;
#pragma unroll
    for (int p = 0; p < PSPAN; p++) maxL = max(maxL, len_sh[p]);

    float c[PSPAN], feat[PSPAN], hreg[PSPAN];
#pragma unroll
    for (int p = 0; p < PSPAN; p++) { c[p] = 0.f; feat[p] = 0.f; hreg[p] = 0.f; }

    int buf = 0;
    for (int s = 0; s < maxL; s++) {
        float a0[PSPAN], a1[PSPAN], a2[PSPAN], a3[PSPAN];
        if (act) {
#pragma unroll
            for (int p = 0; p < PSPAN; p++) {
                int L = len_sh[p];
                int t = dir ? (L - 1 - s) : s;
                if (s >= L) t = 0;
                const float* z = Zd + ((size_t)sp_sh[p] * T_ + t) * G4H;
                a0[p] = z[u];
                a1[p] = z[H_ + u];
                a2[p] = z[2 * H_ + u];
                a3[p] = z[3 * H_ + u];
            }
#pragma unroll 2
            for (int k = 0; k < H_; k += 4) {
                float4 w0 = Wp[(k + 0) * H_ + u];
                float4 w1 = Wp[(k + 1) * H_ + u];
                float4 w2 = Wp[(k + 2) * H_ + u];
                float4 w3 = Wp[(k + 3) * H_ + u];
#pragma unroll
                for (int p = 0; p < PSPAN; p++) {
                    float4 hv = h4[buf][p][k >> 2];
                    a0[p] += w0.x * hv.x; a0[p] += w1.x * hv.y;
                    a0[p] += w2.x * hv.z; a0[p] += w3.x * hv.w;
                    a1[p] += w0.y * hv.x; a1[p] += w1.y * hv.y;
                    a1[p] += w2.y * hv.z; a1[p] += w3.y * hv.w;
                    a2[p] += w0.z * hv.x; a2[p] += w1.z * hv.y;
                    a2[p] += w2.z * hv.z; a2[p] += w3.z * hv.w;
                    a3[p] += w0.w * hv.x; a3[p] += w1.w * hv.y;
                    a3[p] += w2.w * hv.z; a3[p] += w3.w * hv.w;
                }
            }
#pragma unroll
            for (int p = 0; p < PSPAN; p++) {
                if (s < len_sh[p]) {
                    float ig = fast_sig(a0[p]);
                    float fg = fast_sig(a1[p]);
                    float gg = fast_tanh(a2[p]);
                    float og = fast_sig(a3[p]);
                    float cn = fg * c[p] + ig * gg;
                    c[p] = cn;
                    hreg[p] = og * fast_tanh(cn);
                    feat[p] += hreg[p];
                }
                ((float*)&h4[buf ^ 1][p][0])[u] = hreg[p];
            }
        }
        __syncthreads();
        buf ^= 1;
    }

    if (act) {
#pragma unroll
        for (int p = 0; p < PSPAN; p++)
            g_feats[(size_t)sp_sh[p] * (2 * H_) + dir * H_ + u] = feat[p];
    }
}

// ---------------------------------------------------------------------------
// logits
// ---------------------------------------------------------------------------
__global__ __launch_bounds__(192) void logits_kernel(const float* __restrict__ slot_embs,
                                                     const float* __restrict__ slot_mask,
                                                     float* __restrict__ out) {
    __shared__ float f_sm[16][2 * H_];
    __shared__ float se_sm[2 * H_ * NS_];

    int tid = threadIdx.x;
    int n0  = blockIdx.x * 16;

    for (int i = tid; i < 2 * H_ * NS_; i += blockDim.x) se_sm[i] = slot_embs[i];
    for (int i = tid; i < 16 * 2 * H_; i += blockDim.x) {
        int sp = i / (2 * H_), h = i % (2 * H_);
        f_sm[sp][h] = g_feats[(size_t)(n0 + sp) * (2 * H_) + h];
    }
    __syncthreads();

    int sp = tid / NS_, ns = tid % NS_;
    float acc = 0.f;
#pragma unroll 8
    for (int h = 0; h < 2 * H_; h++) acc += f_sm[sp][h] * se_sm[h * NS_ + ns];
    out[(n0 + sp) * NS_ + ns] = acc * slot_mask[n0 + sp];
}

// ---------------------------------------------------------------------------
extern "C" void kernel_launch(void* const* d_in, const int* in_sizes, int n_in,
                              void* d_out, int out_size) {
    const float* hidden    = (const float*)d_in[0];
    const float* Wih_f     = (const float*)d_in[1];
    const float* Whh_f     = (const float*)d_in[2];
    const float* bih_f     = (const float*)d_in[3];
    const float* bhh_f     = (const float*)d_in[4];
    const float* Wih_b     = (const float*)d_in[5];
    const float* Whh_b     = (const float*)d_in[6];
    const float* bih_b     = (const float*)d_in[7];
    const float* bhh_b     = (const float*)d_in[8];
    const float* slot_embs = (const float*)d_in[9];
    const int*   starts    = (const int*)d_in[10];
    const int*   lens      = (const int*)d_in[11];
    const float* slot_mask = (const float*)d_in[12];
    float* out = (float*)d_out;

    const int gemm_smem = 2 * STG * (int)sizeof(unsigned);   // 81920 B
    cudaFuncSetAttribute(gemm_tc, cudaFuncAttributeMaxDynamicSharedMemorySize, gemm_smem);

    pack_kernel<<<1024, 256>>>(Wih_f, Whh_f, bih_f, bhh_f,
                               Wih_b, Whh_b, bih_b, bhh_b);
    prep_kernel<<<1, NSPAN>>>(lens);

    gather_split<<<(MROWS * NSLICE + 255) / 256, 256>>>(hidden, starts);

    dim3 ggrid(NCPAD / 128, MROWS / 128);
    gemm_tc<<<ggrid, 128, gemm_smem>>>();

    dim3 lgrid(128, 2);   // 256 CTAs, descending-length groups
    lstm_kernel<<<lgrid, 224>>>(lens);

    logits_kernel<<<NSPAN / 16, 192>>>(slot_embs, slot_mask, out);
}